// round 15
// baseline (speedup 1.0000x reference)
#include <cuda_runtime.h>
#include <math.h>

#define H48   48
#define NG    8
#define NC    64
#define NB    2304
#define NHWD  110592
#define NOC   256
#define EPSV  1e-5f

// ---- packed fp32x2 helpers (Blackwell FFMA2 — only reachable via PTX) ----
#define FMA_F32X2(d, a, b)   asm("fma.rn.f32x2 %0, %1, %2, %0;" : "+l"(d) : "l"(a), "l"(b))
#define SPLAT_F32X2(d, f)    asm("mov.b64 %0, {%1, %1};" : "=l"(d) : "f"(f))
#define UNPACK_F32X2M(lo, hi, v) asm("mov.b64 {%0, %1}, %2;" : "=f"(lo), "=f"(hi) : "l"(v))

// ---------------- scratch ----------------
__device__ float d_proj[NOC * NHWD];        // [o][b*48 + h]
__device__ float d_outpre[NB * NOC * H48];  // [b][g*1536 + o_local*48 + i]
__device__ float d_psum[NOC], d_psq[NOC];
__device__ float d_ssum[24],  d_ssq[24];
__device__ float d_osum[NOC], d_osq[NOC];
__device__ float d_W1q[8 * 48], d_W1k[8 * 48];
__device__ float d_W2q[36 * 48], d_W2k[36 * 48];

__device__ __forceinline__ void decode_pair(int op, int& a, int& b) {
    a = 0; int r = op;
    while (r >= 7 - a) { r -= 7 - a; a++; }
    b = a + 1 + r;
}

// ------------- pass 0: zero accumulators + rel window tables --------------
__global__ void k_pre(const float* __restrict__ rel) {
    int tid = threadIdx.x;
    if (blockIdx.x == 0) {
        if (tid < NOC) { d_psum[tid] = 0.f; d_psq[tid] = 0.f; d_osum[tid] = 0.f; d_osq[tid] = 0.f; }
        if (tid < 24)  { d_ssum[tid] = 0.f; d_ssq[tid]  = 0.f; }
        for (int idx = tid; idx < 16 * 48; idx += 256) {
            int r = idx / 48, t = idx % 48;
            float s = 0.f;
            for (int d = 0; d < 48; d++) s += rel[r * 95 + t + d];
            if (r < 8) d_W1q[r * 48 + t] = s; else d_W1k[(r - 8) * 48 + t] = s;
        }
    } else {
        for (int idx = tid; idx < 24 * 48; idx += 256) {
            int u = (blockIdx.x - 1) * 24 + idx / 48, t = idx % 48;
            int side = u / 36, p = u % 36;
            int a, b; float f;
            if (p < 8) { a = p; b = p; f = 1.f; } else { decode_pair(p - 8, a, b); f = 2.f; }
            const float* ra = rel + (side * 8 + a) * 95;
            const float* rb = rel + (side * 8 + b) * 95;
            float s = 0.f;
            for (int d = 0; d < 48; d++) s = fmaf(ra[t + d], rb[t + d], s);
            s *= f;
            if (side == 0) d_W2q[p * 48 + t] = s; else d_W2k[p * 48 + t] = s;
        }
    }
}

// ---------------- pass 1: projection GEMM + per-channel stats --------------
__global__ __launch_bounds__(256) void k_proj(const float* __restrict__ x,
                       const float* __restrict__ Wkv,
                       const float* __restrict__ Wq) {
    extern __shared__ float sm[];
    float* Ws = sm;              // 128 x 65
    float* Xs = sm + 128 * 65;   // 64 x 64 : [c][bl*8 + hl]
    int tid = threadIdx.x;
    int ot = blockIdx.x / 1728;
    int rem = blockIdx.x % 1728;
    int bt = rem % 288, ht = rem / 288;
    int b0 = bt * 8, h0 = ht * 8;
    int o_base = ot * 128;

    for (int idx = tid; idx < 128 * 64; idx += 256) {
        int o_loc = idx >> 6, c = idx & 63;
        int o = o_base + o_loc;
        Ws[o_loc * 65 + c] = (o < 192) ? Wkv[o * 64 + c] : Wq[(o - 192) * 64 + c];
    }
    #pragma unroll
    for (int t = 0; t < 16; t++) {
        int idx = t * 256 + tid;
        int c = idx >> 6, sp = idx & 63;
        int hl = sp >> 3, bl = sp & 7;
        Xs[c * 64 + bl * 8 + hl] = x[c * NHWD + (h0 + hl) * 2304 + b0 + bl];
    }
    __syncthreads();

    int og = tid >> 3, bl = tid & 7;
    unsigned long long acc2[4][4];
    #pragma unroll
    for (int i = 0; i < 4; i++)
        #pragma unroll
        for (int j = 0; j < 4; j++) acc2[i][j] = 0ULL;

    const float* xp = Xs + bl * 8;
    const float* wp = Ws + og * 4 * 65;
    #pragma unroll 4
    for (int c = 0; c < 64; c++) {
        ulonglong2 xa = *(const ulonglong2*)(xp + c * 64);
        ulonglong2 xb = *(const ulonglong2*)(xp + c * 64 + 4);
        unsigned long long x2[4] = {xa.x, xa.y, xb.x, xb.y};
        #pragma unroll
        for (int i = 0; i < 4; i++) {
            float wv = wp[i * 65 + c];
            unsigned long long w2; SPLAT_F32X2(w2, wv);
            #pragma unroll
            for (int j = 0; j < 4; j++) FMA_F32X2(acc2[i][j], w2, x2[j]);
        }
    }

    #pragma unroll
    for (int i = 0; i < 4; i++) {
        int o = o_base + og * 4 + i;
        float a[8];
        #pragma unroll
        for (int j = 0; j < 4; j++) UNPACK_F32X2M(a[j * 2], a[j * 2 + 1], acc2[i][j]);
        float s = 0.f, q = 0.f;
        #pragma unroll
        for (int hl = 0; hl < 8; hl++) { s += a[hl]; q += a[hl] * a[hl]; }
        float* base = d_proj + o * NHWD + (b0 + bl) * 48 + h0;
        *(float4*)(base)     = make_float4(a[0], a[1], a[2], a[3]);
        *(float4*)(base + 4) = make_float4(a[4], a[5], a[6], a[7]);
        s += __shfl_down_sync(0xffffffffu, s, 4, 8);
        s += __shfl_down_sync(0xffffffffu, s, 2, 8);
        s += __shfl_down_sync(0xffffffffu, s, 1, 8);
        q += __shfl_down_sync(0xffffffffu, q, 4, 8);
        q += __shfl_down_sync(0xffffffffu, q, 2, 8);
        q += __shfl_down_sync(0xffffffffu, q, 1, 8);
        if (bl == 0) { atomicAdd(&d_psum[o], s); atomicAdd(&d_psq[o], q); }
    }
}

__device__ __forceinline__ void bn_params(float sum, float sq, float n, float gamma, float beta,
                                          float& sc, float& sh) {
    float m = sum / n;
    float var = sq / n - m * m;
    sc = rsqrtf(var + EPSV) * gamma;
    sh = beta - m * sc;
}

// ------------- pass 2: sim BN stats via Gram factorization -----------------
__global__ __launch_bounds__(256) void k_simstat2(const float* __restrict__ fqr_p,
                                                  const float* __restrict__ fkr_p,
                                                  const float* __restrict__ gkv, const float* __restrict__ bkv,
                                                  const float* __restrict__ gq,  const float* __restrict__ bq) {
    __shared__ float qs[64 * 49], ks[64 * 49];
    __shared__ float sW2q[36 * 49], sW2k[36 * 49];
    __shared__ float sW1q[8 * 48], sW1k[8 * 48];
    __shared__ float qsc[64], qsh[64], ksc[64], ksh[64];
    int tid = threadIdx.x;
    int b = blockIdx.x;
    int g = tid >> 5, lane = tid & 31;

    if (tid < 64) {
        int oq = 192 + tid;
        bn_params(d_psum[oq], d_psq[oq], 110592.f, gq[tid], bq[tid], qsc[tid], qsh[tid]);
        int ok = (tid >> 3) * 24 + (tid & 7);
        bn_params(d_psum[ok], d_psq[ok], 110592.f, gkv[ok], bkv[ok], ksc[tid], ksh[tid]);
    }
    __syncthreads();

    for (int idx = tid; idx < 64 * 48; idx += 256) {
        int c64 = idx / 48, h = idx % 48;
        int oq = 192 + c64;
        qs[c64 * 49 + h] = d_proj[oq * NHWD + b * 48 + h] * qsc[c64] + qsh[c64];
        int ok = (c64 >> 3) * 24 + (c64 & 7);
        ks[c64 * 49 + h] = d_proj[ok * NHWD + b * 48 + h] * ksc[c64] + ksh[c64];
    }
    for (int idx = tid; idx < 36 * 48; idx += 256) {
        int p = idx / 48, t = idx % 48;
        sW2q[p * 49 + t] = d_W2q[idx];
        sW2k[p * 49 + t] = d_W2k[idx];
    }
    for (int idx = tid; idx < 8 * 48; idx += 256) { sW1q[idx] = d_W1q[idx]; sW1k[idx] = d_W1k[idx]; }
    __syncthreads();

    float vsumqk = 0.f, vsqqk = 0.f, vtq = 0.f, vtk = 0.f, vsumqr = 0.f, vsumkr = 0.f;

    if (lane < 28) {
        int a, bb2; decode_pair(lane, a, bb2);
        const float* qa = &qs[(g * 8 + a) * 49];
        const float* qb = &qs[(g * 8 + bb2) * 49];
        const float* ka = &ks[(g * 8 + a) * 49];
        const float* kb = &ks[(g * 8 + bb2) * 49];
        const float* w2q = &sW2q[(8 + lane) * 49];
        const float* w2k = &sW2k[(8 + lane) * 49];
        float Qp = 0.f, Kp = 0.f, tq = 0.f, tk = 0.f;
        #pragma unroll 8
        for (int i = 0; i < 48; i++) {
            float qq = qa[i] * qb[i]; Qp += qq; tq = fmaf(qq, w2q[i], tq);
            float kk = ka[i] * kb[i]; Kp += kk; tk = fmaf(kk, w2k[i], tk);
        }
        vsqqk = 2.f * Qp * Kp;
        vtq = tq; vtk = tk;
    }
    if (lane < 8) {
        const float* qc = &qs[(g * 8 + lane) * 49];
        const float* kc = &ks[(g * 8 + lane) * 49];
        const float* w2q = &sW2q[lane * 49];
        const float* w2k = &sW2k[lane * 49];
        const float* w1q = &sW1q[lane * 48];
        const float* w1k = &sW1k[lane * 48];
        float Sq = 0.f, Sk = 0.f, Qd = 0.f, Kd = 0.f, tqd = 0.f, tkd = 0.f, sqr = 0.f, skr = 0.f;
        #pragma unroll 8
        for (int i = 0; i < 48; i++) {
            float qv = qc[i], kv = kc[i];
            Sq += qv; Sk += kv;
            float q2 = qv * qv, k2 = kv * kv;
            Qd += q2; Kd += k2;
            tqd = fmaf(q2, w2q[i], tqd);
            tkd = fmaf(k2, w2k[i], tkd);
            sqr = fmaf(qv, w1q[i], sqr);
            skr = fmaf(kv, w1k[i], skr);
        }
        vsumqk = Sq * Sk;
        vsqqk += Qd * Kd;
        vtq += tqd; vtk += tkd;
        vsumqr = sqr; vsumkr = skr;
    }
    #pragma unroll
    for (int off = 16; off; off >>= 1) {
        vsumqk += __shfl_xor_sync(0xffffffffu, vsumqk, off);
        vsqqk  += __shfl_xor_sync(0xffffffffu, vsqqk,  off);
        vtq    += __shfl_xor_sync(0xffffffffu, vtq,    off);
        vtk    += __shfl_xor_sync(0xffffffffu, vtk,    off);
        vsumqr += __shfl_xor_sync(0xffffffffu, vsumqr, off);
        vsumkr += __shfl_xor_sync(0xffffffffu, vsumkr, off);
    }
    if (lane == 0) {
        float fqr = fqr_p[0], fkr = fkr_p[0];
        atomicAdd(&d_ssum[g], vsumqk);
        atomicAdd(&d_ssq[g],  vsqqk);
        atomicAdd(&d_ssum[8 + g], fqr * vsumqr);
        atomicAdd(&d_ssq[8 + g],  fqr * fqr * vtq);
        atomicAdd(&d_ssum[16 + g], fkr * vsumkr);
        atomicAdd(&d_ssq[16 + g],  fkr * fkr * vtk);
    }
}

// ------- pass 3: two (b) tiles per block, shared rel tables ---------------
// smem (floats):
//   S    [0, 4608)      two logit tiles (stride 48); later 32x49 staging each
//   sq   [4608, 5376)   2 x 8x48
//   sk   [5376, 6144)   2 x 8x48
//   RQ   [6144, 6912)   8x96 cb-scaled rel (shared)
//   RK   [6912, 7680)   8x96 cc2-scaled rel (shared)
//   VE   [7680, 9297)   16x101 (+1 offset) fsve-scaled rel (shared)
//   VS   [9312, 10912)  2 x 16x50 fsv-scaled v
//   sst  [10912, 10976) psc [10976, 11008) psh [11008, 11040)
__global__ __launch_bounds__(256) void k_attn(const float* __restrict__ rel,
                       const float* __restrict__ fqr_p, const float* __restrict__ fkr_p,
                       const float* __restrict__ fsv_p, const float* __restrict__ fsve_p,
                       const float* __restrict__ gkv, const float* __restrict__ bkv,
                       const float* __restrict__ gq,  const float* __restrict__ bq,
                       const float* __restrict__ gsim) {
    __shared__ __align__(16) float sm[11040];
    int tid = threadIdx.x;
    int tile = tid >> 7, t2 = tid & 127;
    int g = blockIdx.x & 7;
    int b = (blockIdx.x >> 3) * 2 + tile;

    float* S   = sm + tile * 2304;
    float* sq  = sm + 4608 + tile * 384;
    float* sk  = sm + 5376 + tile * 384;
    float* RQ  = sm + 6144;
    float* RK  = sm + 6912;
    float* VE  = sm + 7680;
    float* VS  = sm + 9312 + tile * 800;
    float* sst = sm + 10912;
    float* psc = sm + 10976;
    float* psh = sm + 11008;

    if (tid < 64) sst[tid] = 0.f;

    float fqr = fqr_p[0], fkr = fkr_p[0], fsv = fsv_p[0], fsve = fsve_p[0];

    float ca, cb, cc2;
    {
        float n2 = 5308416.f, m, v;
        m = d_ssum[g] / n2;      v = d_ssq[g] / n2 - m * m;      ca  = rsqrtf(v + EPSV) * gsim[g];
        m = d_ssum[8 + g] / n2;  v = d_ssq[8 + g] / n2 - m * m;  cb  = rsqrtf(v + EPSV) * gsim[8 + g]  * fqr;
        m = d_ssum[16 + g] / n2; v = d_ssq[16 + g] / n2 - m * m; cc2 = rsqrtf(v + EPSV) * gsim[16 + g] * fkr;
    }
    if (tid < 32) {
        int o; float gamma, beta;
        if (tid < 8)       { o = 192 + g * 8 + tid;       gamma = gq[o - 192];  beta = bq[o - 192]; }
        else if (tid < 16) { o = g * 24 + (tid - 8);      gamma = gkv[o];       beta = bkv[o]; }
        else               { o = g * 24 + 8 + (tid - 16); gamma = gkv[o];       beta = bkv[o]; }
        bn_params(d_psum[o], d_psq[o], 110592.f, gamma, beta, psc[tid], psh[tid]);
    }
    __syncthreads();

    // per-tile loads (q, k, v) + shared rel tables
    for (int idx = t2; idx < 384; idx += 128) {
        int c = idx / 48, h = idx % 48;
        sq[idx] = d_proj[(192 + g * 8 + c) * NHWD + b * 48 + h] * psc[c] + psh[c];
        sk[idx] = d_proj[(g * 24 + c) * NHWD + b * 48 + h] * psc[8 + c] + psh[8 + c];
    }
    for (int idx = t2; idx < 768; idx += 128) {
        int c = idx / 48, h = idx % 48;
        VS[c * 50 + h] = fsv * (d_proj[(g * 24 + 8 + c) * NHWD + b * 48 + h] * psc[16 + c] + psh[16 + c]);
    }
    for (int idx = tid; idx < 16 * 95; idx += 256) {
        int r = idx / 95, d = idx % 95;
        float v = rel[idx];
        if (r < 8) RQ[r * 96 + d]       = cb  * v;
        else       RK[(r - 8) * 96 + d] = cc2 * v;
    }
    for (int idx = tid; idx < 16 * 95; idx += 256) {
        int r = idx / 95, d = idx % 95;
        VE[r * 101 + d + 1] = fsve * rel[(16 + r) * 95 + d];
    }
    __syncthreads();

    int c0 = (t2 & 7) * 2, i0 = (t2 >> 3) * 3;
    int j0 = (t2 & 7) * 6;

    // Phase A: fused logits
    {
        float L[18];
        #pragma unroll
        for (int e = 0; e < 18; e++) L[e] = 0.f;
        #pragma unroll
        for (int c = 0; c < 8; c++) {
            float qr[3], qa[3], kv[6], rqv[8], rkv[8];
            #pragma unroll
            for (int di = 0; di < 3; di++) { qr[di] = sq[c * 48 + i0 + di]; qa[di] = ca * qr[di]; }
            float2 kv01 = *(const float2*)(sk + c * 48 + j0);
            float2 kv23 = *(const float2*)(sk + c * 48 + j0 + 2);
            float2 kv45 = *(const float2*)(sk + c * 48 + j0 + 4);
            kv[0] = kv01.x; kv[1] = kv01.y; kv[2] = kv23.x;
            kv[3] = kv23.y; kv[4] = kv45.x; kv[5] = kv45.y;
            const float* rqp = RQ + c * 96 + (i0 - j0 + 42);
            const float* rkp = RK + c * 96 + (j0 - i0 + 45);
            #pragma unroll
            for (int t = 0; t < 8; t++) { rqv[t] = rqp[t]; rkv[t] = rkp[t]; }
            #pragma unroll
            for (int di = 0; di < 3; di++)
                #pragma unroll
                for (int dj = 0; dj < 6; dj++) {
                    int e = di * 6 + dj;
                    L[e] = fmaf(kv[dj], qa[di],            L[e]);
                    L[e] = fmaf(kv[dj], rkv[dj + 2 - di],  L[e]);
                    L[e] = fmaf(qr[di], rqv[di + 5 - dj],  L[e]);
                }
        }
        #pragma unroll
        for (int di = 0; di < 3; di++)
            #pragma unroll
            for (int dj = 0; dj < 6; dj++)
                S[(i0 + di) * 48 + (j0 + dj)] = L[di * 6 + dj];
    }
    __syncwarp();   // Phase B rows are warp-private (warp w owns rows 12w..12w+11)

    // Phase B: softmax, one row per 16-lane half-warp
    {
        int w = t2 >> 5, hw = (t2 >> 4) & 1, hl = t2 & 15;
        for (int t = 0; t < 6; t++) {
            int r = w * 12 + t * 2 + hw;
            float a = S[r * 48 + hl];
            float b2 = S[r * 48 + 16 + hl];
            float c3 = S[r * 48 + 32 + hl];
            float m = fmaxf(a, fmaxf(b2, c3));
            #pragma unroll
            for (int off = 8; off; off >>= 1) m = fmaxf(m, __shfl_xor_sync(0xffffffffu, m, off));
            float ea = __expf(a - m), eb = __expf(b2 - m), ec = __expf(c3 - m);
            float s = ea + eb + ec;
            #pragma unroll
            for (int off = 8; off; off >>= 1) s += __shfl_xor_sync(0xffffffffu, s, off);
            float inv = 1.f / s;
            S[r * 48 + hl]      = ea * inv;
            S[r * 48 + 16 + hl] = eb * inv;
            S[r * 48 + 32 + hl] = ec * inv;
        }
    }
    __syncwarp();   // Phase C reads the same warp-private rows

    // Phase C: sv + sve; conflict-free strides (v:50, ve:101)
    float svv[2][3] = {{0.f,0.f,0.f},{0.f,0.f,0.f}};
    float sev[2][3] = {{0.f,0.f,0.f},{0.f,0.f,0.f}};
    {
        const float* Sr0 = &S[i0 * 48];
        const float* Sr1 = &S[(i0 + 1) * 48];
        const float* Sr2 = &S[(i0 + 2) * 48];
        const float* vp0 = VS + c0 * 50;
        const float* vp1 = VS + (c0 + 1) * 50;
        const float* ve0 = VE + c0 * 101 + 1;
        const float* ve1 = VE + (c0 + 1) * 101 + 1;
        float wa0 = ve0[i0 + 47], wa1 = ve0[i0 + 48], wa2 = ve0[i0 + 49];
        float wb0 = ve1[i0 + 47], wb1 = ve1[i0 + 48], wb2 = ve1[i0 + 49];
        #pragma unroll
        for (int jo = 0; jo < 12; jo++) {
            float4 s0q = *(const float4*)(Sr0 + jo * 4);
            float4 s1q = *(const float4*)(Sr1 + jo * 4);
            float4 s2q = *(const float4*)(Sr2 + jo * 4);
            float2 vaA = *(const float2*)(vp0 + jo * 4);
            float2 vaB = *(const float2*)(vp0 + jo * 4 + 2);
            float2 vbA = *(const float2*)(vp1 + jo * 4);
            float2 vbB = *(const float2*)(vp1 + jo * 4 + 2);
            float va4[4] = {vaA.x, vaA.y, vaB.x, vaB.y};
            float vb4[4] = {vbA.x, vbA.y, vbB.x, vbB.y};
            #pragma unroll
            for (int jj = 0; jj < 4; jj++) {
                int j = jo * 4 + jj;
                float sa = (jj == 0) ? s0q.x : (jj == 1) ? s0q.y : (jj == 2) ? s0q.z : s0q.w;
                float sb = (jj == 0) ? s1q.x : (jj == 1) ? s1q.y : (jj == 2) ? s1q.z : s1q.w;
                float sc = (jj == 0) ? s2q.x : (jj == 1) ? s2q.y : (jj == 2) ? s2q.z : s2q.w;
                float va = va4[jj], vb = vb4[jj];
                svv[0][0] = fmaf(sa, va, svv[0][0]);
                svv[0][1] = fmaf(sb, va, svv[0][1]);
                svv[0][2] = fmaf(sc, va, svv[0][2]);
                svv[1][0] = fmaf(sa, vb, svv[1][0]);
                svv[1][1] = fmaf(sb, vb, svv[1][1]);
                svv[1][2] = fmaf(sc, vb, svv[1][2]);
                sev[0][0] = fmaf(sa, wa0, sev[0][0]);
                sev[0][1] = fmaf(sb, wa1, sev[0][1]);
                sev[0][2] = fmaf(sc, wa2, sev[0][2]);
                sev[1][0] = fmaf(sa, wb0, sev[1][0]);
                sev[1][1] = fmaf(sb, wb1, sev[1][1]);
                sev[1][2] = fmaf(sc, wb2, sev[1][2]);
                wa2 = wa1; wa1 = wa0; wa0 = ve0[i0 + 46 - j];
                wb2 = wb1; wb1 = wb0; wb0 = ve1[i0 + 46 - j];
            }
        }
    }

    // out-BN stats: register reduce across threads sharing c0 (both tiles -> one sst)
    {
        float r8[8];
        #pragma unroll
        for (int cl = 0; cl < 2; cl++) {
            float s1 = svv[cl][0] + svv[cl][1] + svv[cl][2];
            float q1 = svv[cl][0]*svv[cl][0] + svv[cl][1]*svv[cl][1] + svv[cl][2]*svv[cl][2];
            float s2 = sev[cl][0] + sev[cl][1] + sev[cl][2];
            float q2 = sev[cl][0]*sev[cl][0] + sev[cl][1]*sev[cl][1] + sev[cl][2]*sev[cl][2];
            r8[cl*4+0] = s1; r8[cl*4+1] = q1; r8[cl*4+2] = s2; r8[cl*4+3] = q2;
        }
        #pragma unroll
        for (int k = 0; k < 8; k++) {
            r8[k] += __shfl_xor_sync(0xffffffffu, r8[k], 8);
            r8[k] += __shfl_xor_sync(0xffffffffu, r8[k], 16);
        }
        if ((tid & 31) < 8) {
            #pragma unroll
            for (int cl = 0; cl < 2; cl++) {
                int o_sv = (c0 + cl) * 2;
                atomicAdd(&sst[o_sv],          r8[cl*4+0]);
                atomicAdd(&sst[32 + o_sv],     r8[cl*4+1]);
                atomicAdd(&sst[o_sv + 1],      r8[cl*4+2]);
                atomicAdd(&sst[32 + o_sv + 1], r8[cl*4+3]);
            }
        }
    }
    __syncthreads();   // S reads done everywhere; sst drained

    // stage into own S region (32 x 49), then coalesced copy out
    #pragma unroll
    for (int cl = 0; cl < 2; cl++) {
        int c = c0 + cl;
        S[(c*2)*49 + i0 + 0]   = svv[cl][0];
        S[(c*2)*49 + i0 + 1]   = svv[cl][1];
        S[(c*2)*49 + i0 + 2]   = svv[cl][2];
        S[(c*2+1)*49 + i0 + 0] = sev[cl][0];
        S[(c*2+1)*49 + i0 + 1] = sev[cl][1];
        S[(c*2+1)*49 + i0 + 2] = sev[cl][2];
    }
    __syncthreads();
    {
        float* dst = d_outpre + (size_t)b * 12288 + g * 1536;
        #pragma unroll
        for (int t = 0; t < 12; t++) {
            int idx = t * 128 + t2;
            dst[idx] = S[(idx / 48) * 49 + idx % 48];
        }
        if (tid < 32) {
            atomicAdd(&d_osum[g * 32 + tid], sst[tid]);
            atomicAdd(&d_osq[g * 32 + tid],  sst[32 + tid]);
        }
    }
}

// ------- pass 4: out BN (inlined) + s-pair sum + transpose -----------------
__global__ void k_out(float* __restrict__ out,
                      const float* __restrict__ gout, const float* __restrict__ bout) {
    __shared__ float tile[48 * 49];
    int tid = threadIdx.x;
    int w = blockIdx.x % 48, gc = blockIdx.x / 48;
    int o0 = gc * 2, o1 = o0 + 1;
    float s0, sh0, s1, sh1;
    bn_params(d_osum[o0], d_osq[o0], 110592.f, gout[o0], bout[o0], s0, sh0);
    bn_params(d_osum[o1], d_osq[o1], 110592.f, gout[o1], bout[o1], s1, sh1);
    float sh = sh0 + sh1;
    #pragma unroll
    for (int t = 0; t < 9; t++) {
        int idx = t * 256 + tid;
        int d = idx / 48, h = idx % 48;
        int bb = w * 48 + d;
        float v = d_outpre[bb * 12288 + o0 * 48 + h] * s0
                + d_outpre[bb * 12288 + o1 * 48 + h] * s1 + sh;
        tile[h * 49 + d] = v;
    }
    __syncthreads();
    #pragma unroll
    for (int t = 0; t < 9; t++) {
        int idx = t * 256 + tid;
        int h = idx / 48, d = idx % 48;
        out[gc * NHWD + h * 2304 + w * 48 + d] = tile[h * 49 + d];
    }
}

// ---------------------------------------------------------------------------
extern "C" void kernel_launch(void* const* d_in, const int* in_sizes, int n_in,
                              void* d_out, int out_size) {
    const float* x    = (const float*)d_in[0];
    const float* Wkv  = (const float*)d_in[1];
    const float* Wq   = (const float*)d_in[2];
    const float* gkv  = (const float*)d_in[3];
    const float* bkv  = (const float*)d_in[4];
    const float* gq   = (const float*)d_in[5];
    const float* bq   = (const float*)d_in[6];
    const float* gsim = (const float*)d_in[7];
    const float* bsim = (const float*)d_in[8];   // shift dropped (softmax invariant)
    const float* gout = (const float*)d_in[9];
    const float* bout = (const float*)d_in[10];
    const float* rel  = (const float*)d_in[11];
    const float* fqr  = (const float*)d_in[12];
    const float* fkr  = (const float*)d_in[13];
    const float* fsv  = (const float*)d_in[14];
    const float* fsve = (const float*)d_in[15];
    (void)bsim;
    float* out = (float*)d_out;

    const int proj_smem = (128 * 65 + 64 * 64) * (int)sizeof(float);  // ~49.6 KB
    cudaFuncSetAttribute(k_proj, cudaFuncAttributeMaxDynamicSharedMemorySize, proj_smem);

    k_pre<<<4, 256>>>(rel);
    k_proj<<<3456, 256, proj_smem>>>(x, Wkv, Wq);
    k_simstat2<<<2304, 256>>>(fqr, fkr, gkv, bkv, gq, bq);
    k_attn<<<9216, 256>>>(rel, fqr, fkr, fsv, fsve, gkv, bkv, gq, bq, gsim);
    k_out<<<6144, 256>>>(out, gout, bout);
}

// round 16
// speedup vs baseline: 1.0697x; 1.0697x over previous
#include <cuda_runtime.h>
#include <cuda_fp16.h>
#include <math.h>

#define H48   48
#define NG    8
#define NC    64
#define NB    2304
#define NHWD  110592
#define NOC   256
#define EPSV  1e-5f

// ---- packed fp32x2 helpers (Blackwell FFMA2 — only reachable via PTX) ----
#define FMA_F32X2(d, a, b)   asm("fma.rn.f32x2 %0, %1, %2, %0;" : "+l"(d) : "l"(a), "l"(b))
#define SPLAT_F32X2(d, f)    asm("mov.b64 %0, {%1, %1};" : "=l"(d) : "f"(f))
#define UNPACK_F32X2M(lo, hi, v) asm("mov.b64 {%0, %1}, %2;" : "=f"(lo), "=f"(hi) : "l"(v))

// ---------------- scratch ----------------
__device__ float  d_proj[NOC * NHWD];        // [o][b*48 + h]
__device__ __half d_outpre[NB * NOC * H48];  // fp16: stats stay fp32 in-register
__device__ float d_psum[NOC], d_psq[NOC];
__device__ float d_ssum[24],  d_ssq[24];
__device__ float d_osum[NOC], d_osq[NOC];
__device__ float d_W1q[8 * 48], d_W1k[8 * 48];
__device__ float d_W2q[36 * 48], d_W2k[36 * 48];

__device__ __forceinline__ void decode_pair(int op, int& a, int& b) {
    a = 0; int r = op;
    while (r >= 7 - a) { r -= 7 - a; a++; }
    b = a + 1 + r;
}

// ------------- pass 0: zero accumulators + rel window tables --------------
__global__ void k_pre(const float* __restrict__ rel) {
    int tid = threadIdx.x;
    if (blockIdx.x == 0) {
        if (tid < NOC) { d_psum[tid] = 0.f; d_psq[tid] = 0.f; d_osum[tid] = 0.f; d_osq[tid] = 0.f; }
        if (tid < 24)  { d_ssum[tid] = 0.f; d_ssq[tid]  = 0.f; }
        for (int idx = tid; idx < 16 * 48; idx += 256) {
            int r = idx / 48, t = idx % 48;
            float s = 0.f;
            for (int d = 0; d < 48; d++) s += rel[r * 95 + t + d];
            if (r < 8) d_W1q[r * 48 + t] = s; else d_W1k[(r - 8) * 48 + t] = s;
        }
    } else {
        for (int idx = tid; idx < 24 * 48; idx += 256) {
            int u = (blockIdx.x - 1) * 24 + idx / 48, t = idx % 48;
            int side = u / 36, p = u % 36;
            int a, b; float f;
            if (p < 8) { a = p; b = p; f = 1.f; } else { decode_pair(p - 8, a, b); f = 2.f; }
            const float* ra = rel + (side * 8 + a) * 95;
            const float* rb = rel + (side * 8 + b) * 95;
            float s = 0.f;
            for (int d = 0; d < 48; d++) s = fmaf(ra[t + d], rb[t + d], s);
            s *= f;
            if (side == 0) d_W2q[p * 48 + t] = s; else d_W2k[p * 48 + t] = s;
        }
    }
}

// ---------------- pass 1: projection GEMM + per-channel stats --------------
__global__ __launch_bounds__(256) void k_proj(const float* __restrict__ x,
                       const float* __restrict__ Wkv,
                       const float* __restrict__ Wq) {
    extern __shared__ float sm[];
    float* Ws = sm;              // 128 x 65
    float* Xs = sm + 128 * 65;   // 64 x 64 : [c][bl*8 + hl]
    int tid = threadIdx.x;
    int ot = blockIdx.x / 1728;
    int rem = blockIdx.x % 1728;
    int bt = rem % 288, ht = rem / 288;
    int b0 = bt * 8, h0 = ht * 8;
    int o_base = ot * 128;

    for (int idx = tid; idx < 128 * 64; idx += 256) {
        int o_loc = idx >> 6, c = idx & 63;
        int o = o_base + o_loc;
        Ws[o_loc * 65 + c] = (o < 192) ? Wkv[o * 64 + c] : Wq[(o - 192) * 64 + c];
    }
    #pragma unroll
    for (int t = 0; t < 16; t++) {
        int idx = t * 256 + tid;
        int c = idx >> 6, sp = idx & 63;
        int hl = sp >> 3, bl = sp & 7;
        Xs[c * 64 + bl * 8 + hl] = x[c * NHWD + (h0 + hl) * 2304 + b0 + bl];
    }
    __syncthreads();

    int og = tid >> 3, bl = tid & 7;
    unsigned long long acc2[4][4];
    #pragma unroll
    for (int i = 0; i < 4; i++)
        #pragma unroll
        for (int j = 0; j < 4; j++) acc2[i][j] = 0ULL;

    const float* xp = Xs + bl * 8;
    const float* wp = Ws + og * 4 * 65;
    #pragma unroll 4
    for (int c = 0; c < 64; c++) {
        ulonglong2 xa = *(const ulonglong2*)(xp + c * 64);
        ulonglong2 xb = *(const ulonglong2*)(xp + c * 64 + 4);
        unsigned long long x2[4] = {xa.x, xa.y, xb.x, xb.y};
        #pragma unroll
        for (int i = 0; i < 4; i++) {
            float wv = wp[i * 65 + c];
            unsigned long long w2; SPLAT_F32X2(w2, wv);
            #pragma unroll
            for (int j = 0; j < 4; j++) FMA_F32X2(acc2[i][j], w2, x2[j]);
        }
    }

    #pragma unroll
    for (int i = 0; i < 4; i++) {
        int o = o_base + og * 4 + i;
        float a[8];
        #pragma unroll
        for (int j = 0; j < 4; j++) UNPACK_F32X2M(a[j * 2], a[j * 2 + 1], acc2[i][j]);
        float s = 0.f, q = 0.f;
        #pragma unroll
        for (int hl = 0; hl < 8; hl++) { s += a[hl]; q += a[hl] * a[hl]; }
        float* base = d_proj + o * NHWD + (b0 + bl) * 48 + h0;
        *(float4*)(base)     = make_float4(a[0], a[1], a[2], a[3]);
        *(float4*)(base + 4) = make_float4(a[4], a[5], a[6], a[7]);
        s += __shfl_down_sync(0xffffffffu, s, 4, 8);
        s += __shfl_down_sync(0xffffffffu, s, 2, 8);
        s += __shfl_down_sync(0xffffffffu, s, 1, 8);
        q += __shfl_down_sync(0xffffffffu, q, 4, 8);
        q += __shfl_down_sync(0xffffffffu, q, 2, 8);
        q += __shfl_down_sync(0xffffffffu, q, 1, 8);
        if (bl == 0) { atomicAdd(&d_psum[o], s); atomicAdd(&d_psq[o], q); }
    }
}

__device__ __forceinline__ void bn_params(float sum, float sq, float n, float gamma, float beta,
                                          float& sc, float& sh) {
    float m = sum / n;
    float var = sq / n - m * m;
    sc = rsqrtf(var + EPSV) * gamma;
    sh = beta - m * sc;
}

// ------------- pass 2: sim BN stats via Gram factorization -----------------
__global__ __launch_bounds__(256) void k_simstat2(const float* __restrict__ fqr_p,
                                                  const float* __restrict__ fkr_p,
                                                  const float* __restrict__ gkv, const float* __restrict__ bkv,
                                                  const float* __restrict__ gq,  const float* __restrict__ bq) {
    __shared__ float qs[64 * 49], ks[64 * 49];
    __shared__ float sW2q[36 * 49], sW2k[36 * 49];
    __shared__ float sW1q[8 * 48], sW1k[8 * 48];
    __shared__ float qsc[64], qsh[64], ksc[64], ksh[64];
    int tid = threadIdx.x;
    int b = blockIdx.x;
    int g = tid >> 5, lane = tid & 31;

    if (tid < 64) {
        int oq = 192 + tid;
        bn_params(d_psum[oq], d_psq[oq], 110592.f, gq[tid], bq[tid], qsc[tid], qsh[tid]);
        int ok = (tid >> 3) * 24 + (tid & 7);
        bn_params(d_psum[ok], d_psq[ok], 110592.f, gkv[ok], bkv[ok], ksc[tid], ksh[tid]);
    }
    __syncthreads();

    for (int idx = tid; idx < 64 * 48; idx += 256) {
        int c64 = idx / 48, h = idx % 48;
        int oq = 192 + c64;
        qs[c64 * 49 + h] = d_proj[oq * NHWD + b * 48 + h] * qsc[c64] + qsh[c64];
        int ok = (c64 >> 3) * 24 + (c64 & 7);
        ks[c64 * 49 + h] = d_proj[ok * NHWD + b * 48 + h] * ksc[c64] + ksh[c64];
    }
    for (int idx = tid; idx < 36 * 48; idx += 256) {
        int p = idx / 48, t = idx % 48;
        sW2q[p * 49 + t] = d_W2q[idx];
        sW2k[p * 49 + t] = d_W2k[idx];
    }
    for (int idx = tid; idx < 8 * 48; idx += 256) { sW1q[idx] = d_W1q[idx]; sW1k[idx] = d_W1k[idx]; }
    __syncthreads();

    float vsumqk = 0.f, vsqqk = 0.f, vtq = 0.f, vtk = 0.f, vsumqr = 0.f, vsumkr = 0.f;

    if (lane < 28) {
        int a, bb2; decode_pair(lane, a, bb2);
        const float* qa = &qs[(g * 8 + a) * 49];
        const float* qb = &qs[(g * 8 + bb2) * 49];
        const float* ka = &ks[(g * 8 + a) * 49];
        const float* kb = &ks[(g * 8 + bb2) * 49];
        const float* w2q = &sW2q[(8 + lane) * 49];
        const float* w2k = &sW2k[(8 + lane) * 49];
        float Qp = 0.f, Kp = 0.f, tq = 0.f, tk = 0.f;
        #pragma unroll 8
        for (int i = 0; i < 48; i++) {
            float qq = qa[i] * qb[i]; Qp += qq; tq = fmaf(qq, w2q[i], tq);
            float kk = ka[i] * kb[i]; Kp += kk; tk = fmaf(kk, w2k[i], tk);
        }
        vsqqk = 2.f * Qp * Kp;
        vtq = tq; vtk = tk;
    }
    if (lane < 8) {
        const float* qc = &qs[(g * 8 + lane) * 49];
        const float* kc = &ks[(g * 8 + lane) * 49];
        const float* w2q = &sW2q[lane * 49];
        const float* w2k = &sW2k[lane * 49];
        const float* w1q = &sW1q[lane * 48];
        const float* w1k = &sW1k[lane * 48];
        float Sq = 0.f, Sk = 0.f, Qd = 0.f, Kd = 0.f, tqd = 0.f, tkd = 0.f, sqr = 0.f, skr = 0.f;
        #pragma unroll 8
        for (int i = 0; i < 48; i++) {
            float qv = qc[i], kv = kc[i];
            Sq += qv; Sk += kv;
            float q2 = qv * qv, k2 = kv * kv;
            Qd += q2; Kd += k2;
            tqd = fmaf(q2, w2q[i], tqd);
            tkd = fmaf(k2, w2k[i], tkd);
            sqr = fmaf(qv, w1q[i], sqr);
            skr = fmaf(kv, w1k[i], skr);
        }
        vsumqk = Sq * Sk;
        vsqqk += Qd * Kd;
        vtq += tqd; vtk += tkd;
        vsumqr = sqr; vsumkr = skr;
    }
    #pragma unroll
    for (int off = 16; off; off >>= 1) {
        vsumqk += __shfl_xor_sync(0xffffffffu, vsumqk, off);
        vsqqk  += __shfl_xor_sync(0xffffffffu, vsqqk,  off);
        vtq    += __shfl_xor_sync(0xffffffffu, vtq,    off);
        vtk    += __shfl_xor_sync(0xffffffffu, vtk,    off);
        vsumqr += __shfl_xor_sync(0xffffffffu, vsumqr, off);
        vsumkr += __shfl_xor_sync(0xffffffffu, vsumkr, off);
    }
    if (lane == 0) {
        float fqr = fqr_p[0], fkr = fkr_p[0];
        atomicAdd(&d_ssum[g], vsumqk);
        atomicAdd(&d_ssq[g],  vsqqk);
        atomicAdd(&d_ssum[8 + g], fqr * vsumqr);
        atomicAdd(&d_ssq[8 + g],  fqr * fqr * vtq);
        atomicAdd(&d_ssum[16 + g], fkr * vsumkr);
        atomicAdd(&d_ssq[16 + g],  fkr * fkr * vtk);
    }
}

// ------- pass 3: two (b) tiles per block, shared rel tables, fp16 out ------
__global__ __launch_bounds__(256) void k_attn(const float* __restrict__ rel,
                       const float* __restrict__ fqr_p, const float* __restrict__ fkr_p,
                       const float* __restrict__ fsv_p, const float* __restrict__ fsve_p,
                       const float* __restrict__ gkv, const float* __restrict__ bkv,
                       const float* __restrict__ gq,  const float* __restrict__ bq,
                       const float* __restrict__ gsim) {
    __shared__ __align__(16) float sm[11040];
    int tid = threadIdx.x;
    int tile = tid >> 7, t2 = tid & 127;
    int g = blockIdx.x & 7;
    int b = (blockIdx.x >> 3) * 2 + tile;

    float* S   = sm + tile * 2304;
    float* sq  = sm + 4608 + tile * 384;
    float* sk  = sm + 5376 + tile * 384;
    float* RQ  = sm + 6144;
    float* RK  = sm + 6912;
    float* VE  = sm + 7680;
    float* VS  = sm + 9312 + tile * 800;
    float* sst = sm + 10912;
    float* psc = sm + 10976;
    float* psh = sm + 11008;

    if (tid < 64) sst[tid] = 0.f;

    float fqr = fqr_p[0], fkr = fkr_p[0], fsv = fsv_p[0], fsve = fsve_p[0];

    float ca, cb, cc2;
    {
        float n2 = 5308416.f, m, v;
        m = d_ssum[g] / n2;      v = d_ssq[g] / n2 - m * m;      ca  = rsqrtf(v + EPSV) * gsim[g];
        m = d_ssum[8 + g] / n2;  v = d_ssq[8 + g] / n2 - m * m;  cb  = rsqrtf(v + EPSV) * gsim[8 + g]  * fqr;
        m = d_ssum[16 + g] / n2; v = d_ssq[16 + g] / n2 - m * m; cc2 = rsqrtf(v + EPSV) * gsim[16 + g] * fkr;
    }
    if (tid < 32) {
        int o; float gamma, beta;
        if (tid < 8)       { o = 192 + g * 8 + tid;       gamma = gq[o - 192];  beta = bq[o - 192]; }
        else if (tid < 16) { o = g * 24 + (tid - 8);      gamma = gkv[o];       beta = bkv[o]; }
        else               { o = g * 24 + 8 + (tid - 16); gamma = gkv[o];       beta = bkv[o]; }
        bn_params(d_psum[o], d_psq[o], 110592.f, gamma, beta, psc[tid], psh[tid]);
    }
    __syncthreads();

    for (int idx = t2; idx < 384; idx += 128) {
        int c = idx / 48, h = idx % 48;
        sq[idx] = d_proj[(192 + g * 8 + c) * NHWD + b * 48 + h] * psc[c] + psh[c];
        sk[idx] = d_proj[(g * 24 + c) * NHWD + b * 48 + h] * psc[8 + c] + psh[8 + c];
    }
    for (int idx = t2; idx < 768; idx += 128) {
        int c = idx / 48, h = idx % 48;
        VS[c * 50 + h] = fsv * (d_proj[(g * 24 + 8 + c) * NHWD + b * 48 + h] * psc[16 + c] + psh[16 + c]);
    }
    for (int idx = tid; idx < 16 * 95; idx += 256) {
        int r = idx / 95, d = idx % 95;
        float v = rel[idx];
        if (r < 8) RQ[r * 96 + d]       = cb  * v;
        else       RK[(r - 8) * 96 + d] = cc2 * v;
    }
    for (int idx = tid; idx < 16 * 95; idx += 256) {
        int r = idx / 95, d = idx % 95;
        VE[r * 101 + d + 1] = fsve * rel[(16 + r) * 95 + d];
    }
    __syncthreads();

    int c0 = (t2 & 7) * 2, i0 = (t2 >> 3) * 3;
    int j0 = (t2 & 7) * 6;

    // Phase A: fused logits
    {
        float L[18];
        #pragma unroll
        for (int e = 0; e < 18; e++) L[e] = 0.f;
        #pragma unroll
        for (int c = 0; c < 8; c++) {
            float qr[3], qa[3], kv[6], rqv[8], rkv[8];
            #pragma unroll
            for (int di = 0; di < 3; di++) { qr[di] = sq[c * 48 + i0 + di]; qa[di] = ca * qr[di]; }
            float2 kv01 = *(const float2*)(sk + c * 48 + j0);
            float2 kv23 = *(const float2*)(sk + c * 48 + j0 + 2);
            float2 kv45 = *(const float2*)(sk + c * 48 + j0 + 4);
            kv[0] = kv01.x; kv[1] = kv01.y; kv[2] = kv23.x;
            kv[3] = kv23.y; kv[4] = kv45.x; kv[5] = kv45.y;
            const float* rqp = RQ + c * 96 + (i0 - j0 + 42);
            const float* rkp = RK + c * 96 + (j0 - i0 + 45);
            #pragma unroll
            for (int t = 0; t < 8; t++) { rqv[t] = rqp[t]; rkv[t] = rkp[t]; }
            #pragma unroll
            for (int di = 0; di < 3; di++)
                #pragma unroll
                for (int dj = 0; dj < 6; dj++) {
                    int e = di * 6 + dj;
                    L[e] = fmaf(kv[dj], qa[di],            L[e]);
                    L[e] = fmaf(kv[dj], rkv[dj + 2 - di],  L[e]);
                    L[e] = fmaf(qr[di], rqv[di + 5 - dj],  L[e]);
                }
        }
        #pragma unroll
        for (int di = 0; di < 3; di++)
            #pragma unroll
            for (int dj = 0; dj < 6; dj++)
                S[(i0 + di) * 48 + (j0 + dj)] = L[di * 6 + dj];
    }
    __syncwarp();   // Phase B rows are warp-private (warp w owns rows 12w..12w+11)

    // Phase B: softmax, one row per 16-lane half-warp
    {
        int w = t2 >> 5, hw = (t2 >> 4) & 1, hl = t2 & 15;
        for (int t = 0; t < 6; t++) {
            int r = w * 12 + t * 2 + hw;
            float a = S[r * 48 + hl];
            float b2 = S[r * 48 + 16 + hl];
            float c3 = S[r * 48 + 32 + hl];
            float m = fmaxf(a, fmaxf(b2, c3));
            #pragma unroll
            for (int off = 8; off; off >>= 1) m = fmaxf(m, __shfl_xor_sync(0xffffffffu, m, off));
            float ea = __expf(a - m), eb = __expf(b2 - m), ec = __expf(c3 - m);
            float s = ea + eb + ec;
            #pragma unroll
            for (int off = 8; off; off >>= 1) s += __shfl_xor_sync(0xffffffffu, s, off);
            float inv = 1.f / s;
            S[r * 48 + hl]      = ea * inv;
            S[r * 48 + 16 + hl] = eb * inv;
            S[r * 48 + 32 + hl] = ec * inv;
        }
    }
    __syncwarp();   // Phase C reads the same warp-private rows

    // Phase C: sv + sve; conflict-free strides (v:50, ve:101)
    float svv[2][3] = {{0.f,0.f,0.f},{0.f,0.f,0.f}};
    float sev[2][3] = {{0.f,0.f,0.f},{0.f,0.f,0.f}};
    {
        const float* Sr0 = &S[i0 * 48];
        const float* Sr1 = &S[(i0 + 1) * 48];
        const float* Sr2 = &S[(i0 + 2) * 48];
        const float* vp0 = VS + c0 * 50;
        const float* vp1 = VS + (c0 + 1) * 50;
        const float* ve0 = VE + c0 * 101 + 1;
        const float* ve1 = VE + (c0 + 1) * 101 + 1;
        float wa0 = ve0[i0 + 47], wa1 = ve0[i0 + 48], wa2 = ve0[i0 + 49];
        float wb0 = ve1[i0 + 47], wb1 = ve1[i0 + 48], wb2 = ve1[i0 + 49];
        #pragma unroll
        for (int jo = 0; jo < 12; jo++) {
            float4 s0q = *(const float4*)(Sr0 + jo * 4);
            float4 s1q = *(const float4*)(Sr1 + jo * 4);
            float4 s2q = *(const float4*)(Sr2 + jo * 4);
            float2 vaA = *(const float2*)(vp0 + jo * 4);
            float2 vaB = *(const float2*)(vp0 + jo * 4 + 2);
            float2 vbA = *(const float2*)(vp1 + jo * 4);
            float2 vbB = *(const float2*)(vp1 + jo * 4 + 2);
            float va4[4] = {vaA.x, vaA.y, vaB.x, vaB.y};
            float vb4[4] = {vbA.x, vbA.y, vbB.x, vbB.y};
            #pragma unroll
            for (int jj = 0; jj < 4; jj++) {
                int j = jo * 4 + jj;
                float sa = (jj == 0) ? s0q.x : (jj == 1) ? s0q.y : (jj == 2) ? s0q.z : s0q.w;
                float sb = (jj == 0) ? s1q.x : (jj == 1) ? s1q.y : (jj == 2) ? s1q.z : s1q.w;
                float sc = (jj == 0) ? s2q.x : (jj == 1) ? s2q.y : (jj == 2) ? s2q.z : s2q.w;
                float va = va4[jj], vb = vb4[jj];
                svv[0][0] = fmaf(sa, va, svv[0][0]);
                svv[0][1] = fmaf(sb, va, svv[0][1]);
                svv[0][2] = fmaf(sc, va, svv[0][2]);
                svv[1][0] = fmaf(sa, vb, svv[1][0]);
                svv[1][1] = fmaf(sb, vb, svv[1][1]);
                svv[1][2] = fmaf(sc, vb, svv[1][2]);
                sev[0][0] = fmaf(sa, wa0, sev[0][0]);
                sev[0][1] = fmaf(sb, wa1, sev[0][1]);
                sev[0][2] = fmaf(sc, wa2, sev[0][2]);
                sev[1][0] = fmaf(sa, wb0, sev[1][0]);
                sev[1][1] = fmaf(sb, wb1, sev[1][1]);
                sev[1][2] = fmaf(sc, wb2, sev[1][2]);
                wa2 = wa1; wa1 = wa0; wa0 = ve0[i0 + 46 - j];
                wb2 = wb1; wb1 = wb0; wb0 = ve1[i0 + 46 - j];
            }
        }
    }

    // out-BN stats: register reduce across threads sharing c0 (exact fp32)
    {
        float r8[8];
        #pragma unroll
        for (int cl = 0; cl < 2; cl++) {
            float s1 = svv[cl][0] + svv[cl][1] + svv[cl][2];
            float q1 = svv[cl][0]*svv[cl][0] + svv[cl][1]*svv[cl][1] + svv[cl][2]*svv[cl][2];
            float s2 = sev[cl][0] + sev[cl][1] + sev[cl][2];
            float q2 = sev[cl][0]*sev[cl][0] + sev[cl][1]*sev[cl][1] + sev[cl][2]*sev[cl][2];
            r8[cl*4+0] = s1; r8[cl*4+1] = q1; r8[cl*4+2] = s2; r8[cl*4+3] = q2;
        }
        #pragma unroll
        for (int k = 0; k < 8; k++) {
            r8[k] += __shfl_xor_sync(0xffffffffu, r8[k], 8);
            r8[k] += __shfl_xor_sync(0xffffffffu, r8[k], 16);
        }
        if ((tid & 31) < 8) {
            #pragma unroll
            for (int cl = 0; cl < 2; cl++) {
                int o_sv = (c0 + cl) * 2;
                atomicAdd(&sst[o_sv],          r8[cl*4+0]);
                atomicAdd(&sst[32 + o_sv],     r8[cl*4+1]);
                atomicAdd(&sst[o_sv + 1],      r8[cl*4+2]);
                atomicAdd(&sst[32 + o_sv + 1], r8[cl*4+3]);
            }
        }
    }
    __syncthreads();

    // stage into own S region (32 x 49), then coalesced fp16 copy out
    #pragma unroll
    for (int cl = 0; cl < 2; cl++) {
        int c = c0 + cl;
        S[(c*2)*49 + i0 + 0]   = svv[cl][0];
        S[(c*2)*49 + i0 + 1]   = svv[cl][1];
        S[(c*2)*49 + i0 + 2]   = svv[cl][2];
        S[(c*2+1)*49 + i0 + 0] = sev[cl][0];
        S[(c*2+1)*49 + i0 + 1] = sev[cl][1];
        S[(c*2+1)*49 + i0 + 2] = sev[cl][2];
    }
    __syncthreads();
    {
        __half2* dst = (__half2*)(d_outpre + (size_t)b * 12288 + g * 1536);
        #pragma unroll
        for (int t = 0; t < 6; t++) {
            int idx2 = (t * 128 + t2) * 2;     // even element index
            int r = idx2 / 48, ccol = idx2 % 48;
            dst[idx2 >> 1] = __floats2half2_rn(S[r * 49 + ccol], S[r * 49 + ccol + 1]);
        }
        if (tid < 32) {
            atomicAdd(&d_osum[g * 32 + tid], sst[tid]);
            atomicAdd(&d_osq[g * 32 + tid],  sst[32 + tid]);
        }
    }
}

// ------- pass 4: out BN (inlined) + s-pair sum + transpose (fp16 in) -------
__global__ void k_out(float* __restrict__ out,
                      const float* __restrict__ gout, const float* __restrict__ bout) {
    __shared__ float tile[48 * 49];
    int tid = threadIdx.x;
    int w = blockIdx.x % 48, gc = blockIdx.x / 48;
    int o0 = gc * 2, o1 = o0 + 1;
    float s0, sh0, s1, sh1;
    bn_params(d_osum[o0], d_osq[o0], 110592.f, gout[o0], bout[o0], s0, sh0);
    bn_params(d_osum[o1], d_osq[o1], 110592.f, gout[o1], bout[o1], s1, sh1);
    float sh = sh0 + sh1;
    #pragma unroll
    for (int t = 0; t < 9; t++) {
        int idx = t * 256 + tid;
        int d = idx / 48, h = idx % 48;
        int bb = w * 48 + d;
        float v = __half2float(d_outpre[bb * 12288 + o0 * 48 + h]) * s0
                + __half2float(d_outpre[bb * 12288 + o1 * 48 + h]) * s1 + sh;
        tile[h * 49 + d] = v;
    }
    __syncthreads();
    #pragma unroll
    for (int t = 0; t < 9; t++) {
        int idx = t * 256 + tid;
        int h = idx / 48, d = idx % 48;
        out[gc * NHWD + h * 2304 + w * 48 + d] = tile[h * 49 + d];
    }
}

// ---------------------------------------------------------------------------
extern "C" void kernel_launch(void* const* d_in, const int* in_sizes, int n_in,
                              void* d_out, int out_size) {
    const float* x    = (const float*)d_in[0];
    const float* Wkv  = (const float*)d_in[1];
    const float* Wq   = (const float*)d_in[2];
    const float* gkv  = (const float*)d_in[3];
    const float* bkv  = (const float*)d_in[4];
    const float* gq   = (const float*)d_in[5];
    const float* bq   = (const float*)d_in[6];
    const float* gsim = (const float*)d_in[7];
    const float* bsim = (const float*)d_in[8];   // shift dropped (softmax invariant)
    const float* gout = (const float*)d_in[9];
    const float* bout = (const float*)d_in[10];
    const float* rel  = (const float*)d_in[11];
    const float* fqr  = (const float*)d_in[12];
    const float* fkr  = (const float*)d_in[13];
    const float* fsv  = (const float*)d_in[14];
    const float* fsve = (const float*)d_in[15];
    (void)bsim;
    float* out = (float*)d_out;

    const int proj_smem = (128 * 65 + 64 * 64) * (int)sizeof(float);  // ~49.6 KB
    cudaFuncSetAttribute(k_proj, cudaFuncAttributeMaxDynamicSharedMemorySize, proj_smem);

    k_pre<<<4, 256>>>(rel);
    k_proj<<<3456, 256, proj_smem>>>(x, Wkv, Wq);
    k_simstat2<<<2304, 256>>>(fqr, fkr, gkv, bkv, gq, bq);
    k_attn<<<9216, 256>>>(rel, fqr, fkr, fsv, fsve, gkv, bkv, gq, bq, gsim);
    k_out<<<6144, 256>>>(out, gout, bout);
}

// round 17
// speedup vs baseline: 1.0767x; 1.0065x over previous
#include <cuda_runtime.h>
#include <cuda_fp16.h>
#include <math.h>

#define H48   48
#define NG    8
#define NC    64
#define NB    2304
#define NHWD  110592
#define NOC   256
#define EPSV  1e-5f

// ---- packed fp32x2 helpers (Blackwell FFMA2 — only reachable via PTX) ----
#define FMA_F32X2(d, a, b)   asm("fma.rn.f32x2 %0, %1, %2, %0;" : "+l"(d) : "l"(a), "l"(b))
#define SPLAT_F32X2(d, f)    asm("mov.b64 %0, {%1, %1};" : "=l"(d) : "f"(f))
#define UNPACK_F32X2M(lo, hi, v) asm("mov.b64 {%0, %1}, %2;" : "=f"(lo), "=f"(hi) : "l"(v))

// ---------------- scratch ----------------
__device__ float  d_proj[NOC * NHWD];         // q/k channels fp32 [o][b*48 + h]
__device__ __half d_projv[128 * NHWD];        // v channels fp16 [g*16+cv][b*48 + h]
__device__ __half d_outpre[NB * NOC * H48];   // fp16 (stats stay fp32 in-register)
__device__ float d_psum[NOC], d_psq[NOC];
__device__ float d_ssum[24],  d_ssq[24];
__device__ float d_osum[NOC], d_osq[NOC];
__device__ float d_W1q[8 * 48], d_W1k[8 * 48];
__device__ float d_W2q[36 * 48], d_W2k[36 * 48];

__device__ __forceinline__ void decode_pair(int op, int& a, int& b) {
    a = 0; int r = op;
    while (r >= 7 - a) { r -= 7 - a; a++; }
    b = a + 1 + r;
}

// ------------- pass 0: zero accumulators + rel window tables --------------
__global__ void k_pre(const float* __restrict__ rel) {
    int tid = threadIdx.x;
    if (blockIdx.x == 0) {
        if (tid < NOC) { d_psum[tid] = 0.f; d_psq[tid] = 0.f; d_osum[tid] = 0.f; d_osq[tid] = 0.f; }
        if (tid < 24)  { d_ssum[tid] = 0.f; d_ssq[tid]  = 0.f; }
        for (int idx = tid; idx < 16 * 48; idx += 256) {
            int r = idx / 48, t = idx % 48;
            float s = 0.f;
            for (int d = 0; d < 48; d++) s += rel[r * 95 + t + d];
            if (r < 8) d_W1q[r * 48 + t] = s; else d_W1k[(r - 8) * 48 + t] = s;
        }
    } else {
        for (int idx = tid; idx < 24 * 48; idx += 256) {
            int u = (blockIdx.x - 1) * 24 + idx / 48, t = idx % 48;
            int side = u / 36, p = u % 36;
            int a, b; float f;
            if (p < 8) { a = p; b = p; f = 1.f; } else { decode_pair(p - 8, a, b); f = 2.f; }
            const float* ra = rel + (side * 8 + a) * 95;
            const float* rb = rel + (side * 8 + b) * 95;
            float s = 0.f;
            for (int d = 0; d < 48; d++) s = fmaf(ra[t + d], rb[t + d], s);
            s *= f;
            if (side == 0) d_W2q[p * 48 + t] = s; else d_W2k[p * 48 + t] = s;
        }
    }
}

// ---------------- pass 1: projection GEMM + per-channel stats --------------
__global__ __launch_bounds__(256) void k_proj(const float* __restrict__ x,
                       const float* __restrict__ Wkv,
                       const float* __restrict__ Wq) {
    extern __shared__ float sm[];
    float* Ws = sm;              // 128 x 65
    float* Xs = sm + 128 * 65;   // 64 x 64 : [c][bl*8 + hl]
    int tid = threadIdx.x;
    int ot = blockIdx.x / 1728;
    int rem = blockIdx.x % 1728;
    int bt = rem % 288, ht = rem / 288;
    int b0 = bt * 8, h0 = ht * 8;
    int o_base = ot * 128;

    for (int idx = tid; idx < 128 * 64; idx += 256) {
        int o_loc = idx >> 6, c = idx & 63;
        int o = o_base + o_loc;
        Ws[o_loc * 65 + c] = (o < 192) ? Wkv[o * 64 + c] : Wq[(o - 192) * 64 + c];
    }
    #pragma unroll
    for (int t = 0; t < 16; t++) {
        int idx = t * 256 + tid;
        int c = idx >> 6, sp = idx & 63;
        int hl = sp >> 3, bl = sp & 7;
        Xs[c * 64 + bl * 8 + hl] = x[c * NHWD + (h0 + hl) * 2304 + b0 + bl];
    }
    __syncthreads();

    int og = tid >> 3, bl = tid & 7;
    unsigned long long acc2[4][4];
    #pragma unroll
    for (int i = 0; i < 4; i++)
        #pragma unroll
        for (int j = 0; j < 4; j++) acc2[i][j] = 0ULL;

    const float* xp = Xs + bl * 8;
    const float* wp = Ws + og * 4 * 65;
    #pragma unroll 4
    for (int c = 0; c < 64; c++) {
        ulonglong2 xa = *(const ulonglong2*)(xp + c * 64);
        ulonglong2 xb = *(const ulonglong2*)(xp + c * 64 + 4);
        unsigned long long x2[4] = {xa.x, xa.y, xb.x, xb.y};
        #pragma unroll
        for (int i = 0; i < 4; i++) {
            float wv = wp[i * 65 + c];
            unsigned long long w2; SPLAT_F32X2(w2, wv);
            #pragma unroll
            for (int j = 0; j < 4; j++) FMA_F32X2(acc2[i][j], w2, x2[j]);
        }
    }

    #pragma unroll
    for (int i = 0; i < 4; i++) {
        int o = o_base + og * 4 + i;
        float a[8];
        #pragma unroll
        for (int j = 0; j < 4; j++) UNPACK_F32X2M(a[j * 2], a[j * 2 + 1], acc2[i][j]);
        float s = 0.f, q = 0.f;
        #pragma unroll
        for (int hl = 0; hl < 8; hl++) { s += a[hl]; q += a[hl] * a[hl]; }

        int om = o % 24;
        if (o < 192 && om >= 8) {
            // v channel: fp16 store only (read exclusively by k_attn Phase C)
            int vidx = (o / 24) * 16 + om - 8;
            __half2 p0 = __floats2half2_rn(a[0], a[1]);
            __half2 p1 = __floats2half2_rn(a[2], a[3]);
            __half2 p2 = __floats2half2_rn(a[4], a[5]);
            __half2 p3 = __floats2half2_rn(a[6], a[7]);
            uint4 u;
            u.x = *(unsigned*)&p0; u.y = *(unsigned*)&p1;
            u.z = *(unsigned*)&p2; u.w = *(unsigned*)&p3;
            *(uint4*)(d_projv + (size_t)vidx * NHWD + (b0 + bl) * 48 + h0) = u;
        } else {
            float* base = d_proj + o * NHWD + (b0 + bl) * 48 + h0;
            *(float4*)(base)     = make_float4(a[0], a[1], a[2], a[3]);
            *(float4*)(base + 4) = make_float4(a[4], a[5], a[6], a[7]);
        }
        s += __shfl_down_sync(0xffffffffu, s, 4, 8);
        s += __shfl_down_sync(0xffffffffu, s, 2, 8);
        s += __shfl_down_sync(0xffffffffu, s, 1, 8);
        q += __shfl_down_sync(0xffffffffu, q, 4, 8);
        q += __shfl_down_sync(0xffffffffu, q, 2, 8);
        q += __shfl_down_sync(0xffffffffu, q, 1, 8);
        if (bl == 0) { atomicAdd(&d_psum[o], s); atomicAdd(&d_psq[o], q); }
    }
}

__device__ __forceinline__ void bn_params(float sum, float sq, float n, float gamma, float beta,
                                          float& sc, float& sh) {
    float m = sum / n;
    float var = sq / n - m * m;
    sc = rsqrtf(var + EPSV) * gamma;
    sh = beta - m * sc;
}

// ------------- pass 2: sim BN stats via Gram factorization -----------------
__global__ __launch_bounds__(256) void k_simstat2(const float* __restrict__ fqr_p,
                                                  const float* __restrict__ fkr_p,
                                                  const float* __restrict__ gkv, const float* __restrict__ bkv,
                                                  const float* __restrict__ gq,  const float* __restrict__ bq) {
    __shared__ float qs[64 * 49], ks[64 * 49];
    __shared__ float sW2q[36 * 49], sW2k[36 * 49];
    __shared__ float sW1q[8 * 48], sW1k[8 * 48];
    __shared__ float qsc[64], qsh[64], ksc[64], ksh[64];
    int tid = threadIdx.x;
    int b = blockIdx.x;
    int g = tid >> 5, lane = tid & 31;

    if (tid < 64) {
        int oq = 192 + tid;
        bn_params(d_psum[oq], d_psq[oq], 110592.f, gq[tid], bq[tid], qsc[tid], qsh[tid]);
        int ok = (tid >> 3) * 24 + (tid & 7);
        bn_params(d_psum[ok], d_psq[ok], 110592.f, gkv[ok], bkv[ok], ksc[tid], ksh[tid]);
    }
    __syncthreads();

    for (int idx = tid; idx < 64 * 48; idx += 256) {
        int c64 = idx / 48, h = idx % 48;
        int oq = 192 + c64;
        qs[c64 * 49 + h] = d_proj[oq * NHWD + b * 48 + h] * qsc[c64] + qsh[c64];
        int ok = (c64 >> 3) * 24 + (c64 & 7);
        ks[c64 * 49 + h] = d_proj[ok * NHWD + b * 48 + h] * ksc[c64] + ksh[c64];
    }
    for (int idx = tid; idx < 36 * 48; idx += 256) {
        int p = idx / 48, t = idx % 48;
        sW2q[p * 49 + t] = d_W2q[idx];
        sW2k[p * 49 + t] = d_W2k[idx];
    }
    for (int idx = tid; idx < 8 * 48; idx += 256) { sW1q[idx] = d_W1q[idx]; sW1k[idx] = d_W1k[idx]; }
    __syncthreads();

    float vsumqk = 0.f, vsqqk = 0.f, vtq = 0.f, vtk = 0.f, vsumqr = 0.f, vsumkr = 0.f;

    if (lane < 28) {
        int a, bb2; decode_pair(lane, a, bb2);
        const float* qa = &qs[(g * 8 + a) * 49];
        const float* qb = &qs[(g * 8 + bb2) * 49];
        const float* ka = &ks[(g * 8 + a) * 49];
        const float* kb = &ks[(g * 8 + bb2) * 49];
        const float* w2q = &sW2q[(8 + lane) * 49];
        const float* w2k = &sW2k[(8 + lane) * 49];
        float Qp = 0.f, Kp = 0.f, tq = 0.f, tk = 0.f;
        #pragma unroll 8
        for (int i = 0; i < 48; i++) {
            float qq = qa[i] * qb[i]; Qp += qq; tq = fmaf(qq, w2q[i], tq);
            float kk = ka[i] * kb[i]; Kp += kk; tk = fmaf(kk, w2k[i], tk);
        }
        vsqqk = 2.f * Qp * Kp;
        vtq = tq; vtk = tk;
    }
    if (lane < 8) {
        const float* qc = &qs[(g * 8 + lane) * 49];
        const float* kc = &ks[(g * 8 + lane) * 49];
        const float* w2q = &sW2q[lane * 49];
        const float* w2k = &sW2k[lane * 49];
        const float* w1q = &sW1q[lane * 48];
        const float* w1k = &sW1k[lane * 48];
        float Sq = 0.f, Sk = 0.f, Qd = 0.f, Kd = 0.f, tqd = 0.f, tkd = 0.f, sqr = 0.f, skr = 0.f;
        #pragma unroll 8
        for (int i = 0; i < 48; i++) {
            float qv = qc[i], kv = kc[i];
            Sq += qv; Sk += kv;
            float q2 = qv * qv, k2 = kv * kv;
            Qd += q2; Kd += k2;
            tqd = fmaf(q2, w2q[i], tqd);
            tkd = fmaf(k2, w2k[i], tkd);
            sqr = fmaf(qv, w1q[i], sqr);
            skr = fmaf(kv, w1k[i], skr);
        }
        vsumqk = Sq * Sk;
        vsqqk += Qd * Kd;
        vtq += tqd; vtk += tkd;
        vsumqr = sqr; vsumkr = skr;
    }
    #pragma unroll
    for (int off = 16; off; off >>= 1) {
        vsumqk += __shfl_xor_sync(0xffffffffu, vsumqk, off);
        vsqqk  += __shfl_xor_sync(0xffffffffu, vsqqk,  off);
        vtq    += __shfl_xor_sync(0xffffffffu, vtq,    off);
        vtk    += __shfl_xor_sync(0xffffffffu, vtk,    off);
        vsumqr += __shfl_xor_sync(0xffffffffu, vsumqr, off);
        vsumkr += __shfl_xor_sync(0xffffffffu, vsumkr, off);
    }
    if (lane == 0) {
        float fqr = fqr_p[0], fkr = fkr_p[0];
        atomicAdd(&d_ssum[g], vsumqk);
        atomicAdd(&d_ssq[g],  vsqqk);
        atomicAdd(&d_ssum[8 + g], fqr * vsumqr);
        atomicAdd(&d_ssq[8 + g],  fqr * fqr * vtq);
        atomicAdd(&d_ssum[16 + g], fkr * vsumkr);
        atomicAdd(&d_ssq[16 + g],  fkr * fkr * vtk);
    }
}

// ------- pass 3: two (b) tiles per block, shared rel, fp16 v + out ---------
__global__ __launch_bounds__(256) void k_attn(const float* __restrict__ rel,
                       const float* __restrict__ fqr_p, const float* __restrict__ fkr_p,
                       const float* __restrict__ fsv_p, const float* __restrict__ fsve_p,
                       const float* __restrict__ gkv, const float* __restrict__ bkv,
                       const float* __restrict__ gq,  const float* __restrict__ bq,
                       const float* __restrict__ gsim) {
    __shared__ __align__(16) float sm[11040];
    int tid = threadIdx.x;
    int tile = tid >> 7, t2 = tid & 127;
    int g = blockIdx.x & 7;
    int b = (blockIdx.x >> 3) * 2 + tile;

    float* S   = sm + tile * 2304;
    float* sq  = sm + 4608 + tile * 384;
    float* sk  = sm + 5376 + tile * 384;
    float* RQ  = sm + 6144;
    float* RK  = sm + 6912;
    float* VE  = sm + 7680;
    float* VS  = sm + 9312 + tile * 800;
    float* sst = sm + 10912;
    float* psc = sm + 10976;
    float* psh = sm + 11008;

    if (tid < 64) sst[tid] = 0.f;

    float fqr = fqr_p[0], fkr = fkr_p[0], fsv = fsv_p[0], fsve = fsve_p[0];

    float ca, cb, cc2;
    {
        float n2 = 5308416.f, m, v;
        m = d_ssum[g] / n2;      v = d_ssq[g] / n2 - m * m;      ca  = rsqrtf(v + EPSV) * gsim[g];
        m = d_ssum[8 + g] / n2;  v = d_ssq[8 + g] / n2 - m * m;  cb  = rsqrtf(v + EPSV) * gsim[8 + g]  * fqr;
        m = d_ssum[16 + g] / n2; v = d_ssq[16 + g] / n2 - m * m; cc2 = rsqrtf(v + EPSV) * gsim[16 + g] * fkr;
    }
    if (tid < 32) {
        int o; float gamma, beta;
        if (tid < 8)       { o = 192 + g * 8 + tid;       gamma = gq[o - 192];  beta = bq[o - 192]; }
        else if (tid < 16) { o = g * 24 + (tid - 8);      gamma = gkv[o];       beta = bkv[o]; }
        else               { o = g * 24 + 8 + (tid - 16); gamma = gkv[o];       beta = bkv[o]; }
        bn_params(d_psum[o], d_psq[o], 110592.f, gamma, beta, psc[tid], psh[tid]);
    }
    __syncthreads();

    for (int idx = t2; idx < 384; idx += 128) {
        int c = idx / 48, h = idx % 48;
        sq[idx] = d_proj[(192 + g * 8 + c) * NHWD + b * 48 + h] * psc[c] + psh[c];
        sk[idx] = d_proj[(g * 24 + c) * NHWD + b * 48 + h] * psc[8 + c] + psh[8 + c];
    }
    for (int idx = t2; idx < 768; idx += 128) {
        int c = idx / 48, h = idx % 48;
        float raw = __half2float(d_projv[(size_t)(g * 16 + c) * NHWD + b * 48 + h]);
        VS[c * 50 + h] = fsv * (raw * psc[16 + c] + psh[16 + c]);
    }
    for (int idx = tid; idx < 16 * 95; idx += 256) {
        int r = idx / 95, d = idx % 95;
        float v = rel[idx];
        if (r < 8) RQ[r * 96 + d]       = cb  * v;
        else       RK[(r - 8) * 96 + d] = cc2 * v;
    }
    for (int idx = tid; idx < 16 * 95; idx += 256) {
        int r = idx / 95, d = idx % 95;
        VE[r * 101 + d + 1] = fsve * rel[(16 + r) * 95 + d];
    }
    __syncthreads();

    int c0 = (t2 & 7) * 2, i0 = (t2 >> 3) * 3;
    int j0 = (t2 & 7) * 6;

    // Phase A: fused logits
    {
        float L[18];
        #pragma unroll
        for (int e = 0; e < 18; e++) L[e] = 0.f;
        #pragma unroll
        for (int c = 0; c < 8; c++) {
            float qr[3], qa[3], kv[6], rqv[8], rkv[8];
            #pragma unroll
            for (int di = 0; di < 3; di++) { qr[di] = sq[c * 48 + i0 + di]; qa[di] = ca * qr[di]; }
            float2 kv01 = *(const float2*)(sk + c * 48 + j0);
            float2 kv23 = *(const float2*)(sk + c * 48 + j0 + 2);
            float2 kv45 = *(const float2*)(sk + c * 48 + j0 + 4);
            kv[0] = kv01.x; kv[1] = kv01.y; kv[2] = kv23.x;
            kv[3] = kv23.y; kv[4] = kv45.x; kv[5] = kv45.y;
            const float* rqp = RQ + c * 96 + (i0 - j0 + 42);
            const float* rkp = RK + c * 96 + (j0 - i0 + 45);
            #pragma unroll
            for (int t = 0; t < 8; t++) { rqv[t] = rqp[t]; rkv[t] = rkp[t]; }
            #pragma unroll
            for (int di = 0; di < 3; di++)
                #pragma unroll
                for (int dj = 0; dj < 6; dj++) {
                    int e = di * 6 + dj;
                    L[e] = fmaf(kv[dj], qa[di],            L[e]);
                    L[e] = fmaf(kv[dj], rkv[dj + 2 - di],  L[e]);
                    L[e] = fmaf(qr[di], rqv[di + 5 - dj],  L[e]);
                }
        }
        #pragma unroll
        for (int di = 0; di < 3; di++)
            #pragma unroll
            for (int dj = 0; dj < 6; dj++)
                S[(i0 + di) * 48 + (j0 + dj)] = L[di * 6 + dj];
    }
    __syncwarp();   // Phase B rows are warp-private (warp w owns rows 12w..12w+11)

    // Phase B: softmax, one row per 16-lane half-warp
    {
        int w = t2 >> 5, hw = (t2 >> 4) & 1, hl = t2 & 15;
        for (int t = 0; t < 6; t++) {
            int r = w * 12 + t * 2 + hw;
            float a = S[r * 48 + hl];
            float b2 = S[r * 48 + 16 + hl];
            float c3 = S[r * 48 + 32 + hl];
            float m = fmaxf(a, fmaxf(b2, c3));
            #pragma unroll
            for (int off = 8; off; off >>= 1) m = fmaxf(m, __shfl_xor_sync(0xffffffffu, m, off));
            float ea = __expf(a - m), eb = __expf(b2 - m), ec = __expf(c3 - m);
            float s = ea + eb + ec;
            #pragma unroll
            for (int off = 8; off; off >>= 1) s += __shfl_xor_sync(0xffffffffu, s, off);
            float inv = 1.f / s;
            S[r * 48 + hl]      = ea * inv;
            S[r * 48 + 16 + hl] = eb * inv;
            S[r * 48 + 32 + hl] = ec * inv;
        }
    }
    __syncwarp();   // Phase C reads the same warp-private rows

    // Phase C: sv + sve; conflict-free strides (v:50, ve:101)
    float svv[2][3] = {{0.f,0.f,0.f},{0.f,0.f,0.f}};
    float sev[2][3] = {{0.f,0.f,0.f},{0.f,0.f,0.f}};
    {
        const float* Sr0 = &S[i0 * 48];
        const float* Sr1 = &S[(i0 + 1) * 48];
        const float* Sr2 = &S[(i0 + 2) * 48];
        const float* vp0 = VS + c0 * 50;
        const float* vp1 = VS + (c0 + 1) * 50;
        const float* ve0 = VE + c0 * 101 + 1;
        const float* ve1 = VE + (c0 + 1) * 101 + 1;
        float wa0 = ve0[i0 + 47], wa1 = ve0[i0 + 48], wa2 = ve0[i0 + 49];
        float wb0 = ve1[i0 + 47], wb1 = ve1[i0 + 48], wb2 = ve1[i0 + 49];
        #pragma unroll
        for (int jo = 0; jo < 12; jo++) {
            float4 s0q = *(const float4*)(Sr0 + jo * 4);
            float4 s1q = *(const float4*)(Sr1 + jo * 4);
            float4 s2q = *(const float4*)(Sr2 + jo * 4);
            float2 vaA = *(const float2*)(vp0 + jo * 4);
            float2 vaB = *(const float2*)(vp0 + jo * 4 + 2);
            float2 vbA = *(const float2*)(vp1 + jo * 4);
            float2 vbB = *(const float2*)(vp1 + jo * 4 + 2);
            float va4[4] = {vaA.x, vaA.y, vaB.x, vaB.y};
            float vb4[4] = {vbA.x, vbA.y, vbB.x, vbB.y};
            #pragma unroll
            for (int jj = 0; jj < 4; jj++) {
                int j = jo * 4 + jj;
                float sa = (jj == 0) ? s0q.x : (jj == 1) ? s0q.y : (jj == 2) ? s0q.z : s0q.w;
                float sb = (jj == 0) ? s1q.x : (jj == 1) ? s1q.y : (jj == 2) ? s1q.z : s1q.w;
                float sc = (jj == 0) ? s2q.x : (jj == 1) ? s2q.y : (jj == 2) ? s2q.z : s2q.w;
                float va = va4[jj], vb = vb4[jj];
                svv[0][0] = fmaf(sa, va, svv[0][0]);
                svv[0][1] = fmaf(sb, va, svv[0][1]);
                svv[0][2] = fmaf(sc, va, svv[0][2]);
                svv[1][0] = fmaf(sa, vb, svv[1][0]);
                svv[1][1] = fmaf(sb, vb, svv[1][1]);
                svv[1][2] = fmaf(sc, vb, svv[1][2]);
                sev[0][0] = fmaf(sa, wa0, sev[0][0]);
                sev[0][1] = fmaf(sb, wa1, sev[0][1]);
                sev[0][2] = fmaf(sc, wa2, sev[0][2]);
                sev[1][0] = fmaf(sa, wb0, sev[1][0]);
                sev[1][1] = fmaf(sb, wb1, sev[1][1]);
                sev[1][2] = fmaf(sc, wb2, sev[1][2]);
                wa2 = wa1; wa1 = wa0; wa0 = ve0[i0 + 46 - j];
                wb2 = wb1; wb1 = wb0; wb0 = ve1[i0 + 46 - j];
            }
        }
    }

    // out-BN stats: register reduce across threads sharing c0 (exact fp32)
    {
        float r8[8];
        #pragma unroll
        for (int cl = 0; cl < 2; cl++) {
            float s1 = svv[cl][0] + svv[cl][1] + svv[cl][2];
            float q1 = svv[cl][0]*svv[cl][0] + svv[cl][1]*svv[cl][1] + svv[cl][2]*svv[cl][2];
            float s2 = sev[cl][0] + sev[cl][1] + sev[cl][2];
            float q2 = sev[cl][0]*sev[cl][0] + sev[cl][1]*sev[cl][1] + sev[cl][2]*sev[cl][2];
            r8[cl*4+0] = s1; r8[cl*4+1] = q1; r8[cl*4+2] = s2; r8[cl*4+3] = q2;
        }
        #pragma unroll
        for (int k = 0; k < 8; k++) {
            r8[k] += __shfl_xor_sync(0xffffffffu, r8[k], 8);
            r8[k] += __shfl_xor_sync(0xffffffffu, r8[k], 16);
        }
        if ((tid & 31) < 8) {
            #pragma unroll
            for (int cl = 0; cl < 2; cl++) {
                int o_sv = (c0 + cl) * 2;
                atomicAdd(&sst[o_sv],          r8[cl*4+0]);
                atomicAdd(&sst[32 + o_sv],     r8[cl*4+1]);
                atomicAdd(&sst[o_sv + 1],      r8[cl*4+2]);
                atomicAdd(&sst[32 + o_sv + 1], r8[cl*4+3]);
            }
        }
    }
    __syncthreads();

    // stage into own S region (32 x 49), then coalesced fp16 copy out
    #pragma unroll
    for (int cl = 0; cl < 2; cl++) {
        int c = c0 + cl;
        S[(c*2)*49 + i0 + 0]   = svv[cl][0];
        S[(c*2)*49 + i0 + 1]   = svv[cl][1];
        S[(c*2)*49 + i0 + 2]   = svv[cl][2];
        S[(c*2+1)*49 + i0 + 0] = sev[cl][0];
        S[(c*2+1)*49 + i0 + 1] = sev[cl][1];
        S[(c*2+1)*49 + i0 + 2] = sev[cl][2];
    }
    __syncthreads();
    {
        __half2* dst = (__half2*)(d_outpre + (size_t)b * 12288 + g * 1536);
        #pragma unroll
        for (int t = 0; t < 6; t++) {
            int idx2 = (t * 128 + t2) * 2;
            int r = idx2 / 48, ccol = idx2 % 48;
            dst[idx2 >> 1] = __floats2half2_rn(S[r * 49 + ccol], S[r * 49 + ccol + 1]);
        }
        if (tid < 32) {
            atomicAdd(&d_osum[g * 32 + tid], sst[tid]);
            atomicAdd(&d_osq[g * 32 + tid],  sst[32 + tid]);
        }
    }
}

// ------- pass 4: out BN (inlined) + s-pair sum + transpose (fp16 in) -------
__global__ void k_out(float* __restrict__ out,
                      const float* __restrict__ gout, const float* __restrict__ bout) {
    __shared__ float tile[48 * 49];
    int tid = threadIdx.x;
    int w = blockIdx.x % 48, gc = blockIdx.x / 48;
    int o0 = gc * 2, o1 = o0 + 1;
    float s0, sh0, s1, sh1;
    bn_params(d_osum[o0], d_osq[o0], 110592.f, gout[o0], bout[o0], s0, sh0);
    bn_params(d_osum[o1], d_osq[o1], 110592.f, gout[o1], bout[o1], s1, sh1);
    float sh = sh0 + sh1;
    #pragma unroll
    for (int t = 0; t < 9; t++) {
        int idx = t * 256 + tid;
        int d = idx / 48, h = idx % 48;
        int bb = w * 48 + d;
        float v = __half2float(d_outpre[bb * 12288 + o0 * 48 + h]) * s0
                + __half2float(d_outpre[bb * 12288 + o1 * 48 + h]) * s1 + sh;
        tile[h * 49 + d] = v;
    }
    __syncthreads();
    #pragma unroll
    for (int t = 0; t < 9; t++) {
        int idx = t * 256 + tid;
        int h = idx / 48, d = idx % 48;
        out[gc * NHWD + h * 2304 + w * 48 + d] = tile[h * 49 + d];
    }
}

// ---------------------------------------------------------------------------
extern "C" void kernel_launch(void* const* d_in, const int* in_sizes, int n_in,
                              void* d_out, int out_size) {
    const float* x    = (const float*)d_in[0];
    const float* Wkv  = (const float*)d_in[1];
    const float* Wq   = (const float*)d_in[2];
    const float* gkv  = (const float*)d_in[3];
    const float* bkv  = (const float*)d_in[4];
    const float* gq   = (const float*)d_in[5];
    const float* bq   = (const float*)d_in[6];
    const float* gsim = (const float*)d_in[7];
    const float* bsim = (const float*)d_in[8];   // shift dropped (softmax invariant)
    const float* gout = (const float*)d_in[9];
    const float* bout = (const float*)d_in[10];
    const float* rel  = (const float*)d_in[11];
    const float* fqr  = (const float*)d_in[12];
    const float* fkr  = (const float*)d_in[13];
    const float* fsv  = (const float*)d_in[14];
    const float* fsve = (const float*)d_in[15];
    (void)bsim;
    float* out = (float*)d_out;

    const int proj_smem = (128 * 65 + 64 * 64) * (int)sizeof(float);  // ~49.6 KB
    cudaFuncSetAttribute(k_proj, cudaFuncAttributeMaxDynamicSharedMemorySize, proj_smem);

    k_pre<<<4, 256>>>(rel);
    k_proj<<<3456, 256, proj_smem>>>(x, Wkv, Wq);
    k_simstat2<<<2304, 256>>>(fqr, fkr, gkv, bkv, gq, bq);
    k_attn<<<9216, 256>>>(rel, fqr, fkr, fsv, fsve, gkv, bkv, gq, bq, gsim);
    k_out<<<6144, 256>>>(out, gout, bout);
}